// round 2
// baseline (speedup 1.0000x reference)
#include <cuda_runtime.h>
#include <cuda_bf16.h>

// Scratch: xW = x @ W[64:192] + b   (50000 x 128 f32 = 25.6 MB, L2-resident)
#define MAX_NODES 50000
__device__ float g_xw[(size_t)MAX_NODES * 128];

__device__ __forceinline__ void red_add_v4(float* p, float a, float b, float c, float d) {
    asm volatile("red.global.add.v4.f32 [%0], {%1,%2,%3,%4};"
                 :: "l"(p), "f"(a), "f"(b), "f"(c), "f"(d) : "memory");
}

// ---------------------------------------------------------------------------
// Kernel 1: node precompute  xW[n][o] = b[o] + sum_k x[n][k] * W[64+k][o]
// 128 nodes x 128 outs per block, 256 threads, 8x8 register tile, K in 2x64.
// ---------------------------------------------------------------------------
__global__ void node_xw_kernel(const float* __restrict__ x,
                               const float* __restrict__ W,   // [192][128]
                               const float* __restrict__ b,
                               int N) {
    extern __shared__ float sm[];
    float* x_s = sm;              // [128][64]
    float* W_s = sm + 128 * 64;   // [64][128]

    const int tid = threadIdx.x;
    const int tx = tid & 15;
    const int ty = tid >> 4;
    const int n0 = blockIdx.x * 128;

    float acc[8][8];
#pragma unroll
    for (int i = 0; i < 8; i++)
#pragma unroll
        for (int j = 0; j < 8; j++) acc[i][j] = 0.0f;

    for (int kc = 0; kc < 2; kc++) {
        __syncthreads();
        // load x tile [128 nodes][64 k], coalesced float4
#pragma unroll
        for (int it = 0; it < 8; it++) {
            int i = tid + it * 256;          // 2048 float4 total
            int n = i >> 4, kq = i & 15;
            float4 v = make_float4(0.f, 0.f, 0.f, 0.f);
            if (n0 + n < N)
                v = *(const float4*)&x[(size_t)(n0 + n) * 128 + kc * 64 + kq * 4];
            *(float4*)&x_s[n * 64 + kq * 4] = v;
        }
        // load W chunk rows [64 + kc*64, 64 + kc*64 + 64)
#pragma unroll
        for (int it = 0; it < 8; it++) {
            int i = tid + it * 256;          // 2048 float4 total
            int k = i >> 5, oq = i & 31;
            *(float4*)&W_s[k * 128 + oq * 4] =
                *(const float4*)&W[(size_t)(64 + kc * 64 + k) * 128 + oq * 4];
        }
        __syncthreads();

#pragma unroll 4
        for (int k = 0; k < 64; k++) {
            float a[8];
#pragma unroll
            for (int i = 0; i < 4; i++) {
                a[i]     = x_s[(ty * 4 + i) * 64 + k];
                a[4 + i] = x_s[(64 + ty * 4 + i) * 64 + k];
            }
            float4 w0 = *(float4*)&W_s[k * 128 + tx * 4];
            float4 w1 = *(float4*)&W_s[k * 128 + 64 + tx * 4];
#pragma unroll
            for (int i = 0; i < 8; i++) {
                acc[i][0] += a[i] * w0.x;  acc[i][1] += a[i] * w0.y;
                acc[i][2] += a[i] * w0.z;  acc[i][3] += a[i] * w0.w;
                acc[i][4] += a[i] * w1.x;  acc[i][5] += a[i] * w1.y;
                acc[i][6] += a[i] * w1.z;  acc[i][7] += a[i] * w1.w;
            }
        }
    }

    float4 b0 = *(const float4*)&b[tx * 4];
    float4 b1 = *(const float4*)&b[64 + tx * 4];
#pragma unroll
    for (int i = 0; i < 8; i++) {
        int n = (i < 4) ? (ty * 4 + i) : (64 + ty * 4 + (i - 4));
        if (n0 + n < N) {
            float* p = &g_xw[(size_t)(n0 + n) * 128];
            float4 v0 = make_float4(acc[i][0] + b0.x, acc[i][1] + b0.y,
                                    acc[i][2] + b0.z, acc[i][3] + b0.w);
            float4 v1 = make_float4(acc[i][4] + b1.x, acc[i][5] + b1.y,
                                    acc[i][6] + b1.z, acc[i][7] + b1.w);
            *(float4*)&p[tx * 4]      = v0;
            *(float4*)&p[64 + tx * 4] = v1;
        }
    }
}

// ---------------------------------------------------------------------------
// Kernel 2: edge GEMM + gather + ReLU + scatter-add
// msg = relu(edge_attr @ W[0:64] + xW[src]); out[dst] += msg (vector atomics)
// 128 edges x 128 outs per block, 256 threads, 8x8 register tile, K = 64.
// edge_index is int32 [2][E] (JAX default x64-disabled downcasts int64->int32).
// ---------------------------------------------------------------------------
__global__ void edge_kernel(const int* __restrict__ eidx,  // [2][E] int32
                            const float* __restrict__ ea,  // [E][64]
                            const float* __restrict__ W,   // [192][128]
                            float* __restrict__ out,       // [N][128]
                            int E, int N) {
    extern __shared__ float sm[];
    float* W_s  = sm;            // [64][128]
    float* ea_s = sm + 8192;     // [128][64]
    int*   src_s = (int*)(sm + 16384);
    int*   dst_s = src_s + 128;

    const int tid = threadIdx.x;
    const int tx = tid & 15;
    const int ty = tid >> 4;
    const int e0 = blockIdx.x * 128;

    // load W rows 0..63 (edge part of the weight)
#pragma unroll
    for (int it = 0; it < 8; it++) {
        int i = tid + it * 256;          // 2048 float4
        int k = i >> 5, oq = i & 31;
        *(float4*)&W_s[k * 128 + oq * 4] =
            *(const float4*)&W[(size_t)k * 128 + oq * 4];
    }
    // load edge_attr tile [128][64], coalesced float4
#pragma unroll
    for (int it = 0; it < 8; it++) {
        int i = tid + it * 256;          // 2048 float4
        int e = i >> 4, kq = i & 15;
        float4 v = make_float4(0.f, 0.f, 0.f, 0.f);
        if (e0 + e < E)
            v = *(const float4*)&ea[(size_t)(e0 + e) * 64 + kq * 4];
        *(float4*)&ea_s[e * 64 + kq * 4] = v;
    }
    if (tid < 128) {
        int e = e0 + tid;
        src_s[tid] = (e < E) ? eidx[e] : -1;
        dst_s[tid] = (e < E) ? eidx[(size_t)E + e] : -1;
    }
    __syncthreads();

    float acc[8][8];
#pragma unroll
    for (int i = 0; i < 8; i++)
#pragma unroll
        for (int j = 0; j < 8; j++) acc[i][j] = 0.0f;

#pragma unroll 4
    for (int k = 0; k < 64; k++) {
        float a[8];
#pragma unroll
        for (int i = 0; i < 4; i++) {
            a[i]     = ea_s[(ty * 4 + i) * 64 + k];
            a[4 + i] = ea_s[(64 + ty * 4 + i) * 64 + k];
        }
        float4 w0 = *(float4*)&W_s[k * 128 + tx * 4];
        float4 w1 = *(float4*)&W_s[k * 128 + 64 + tx * 4];
#pragma unroll
        for (int i = 0; i < 8; i++) {
            acc[i][0] += a[i] * w0.x;  acc[i][1] += a[i] * w0.y;
            acc[i][2] += a[i] * w0.z;  acc[i][3] += a[i] * w0.w;
            acc[i][4] += a[i] * w1.x;  acc[i][5] += a[i] * w1.y;
            acc[i][6] += a[i] * w1.z;  acc[i][7] += a[i] * w1.w;
        }
    }

    // epilogue: gather xW[src] (L2-resident), ReLU, vector atomic scatter
#pragma unroll
    for (int i = 0; i < 8; i++) {
        int le = (i < 4) ? (ty * 4 + i) : (64 + ty * 4 + (i - 4));
        if (e0 + le >= E) continue;
        int s = src_s[le];
        int d = dst_s[le];
        // defensive bounds (prevents illegal access on any index surprise;
        // a real violation would surface as rel_err instead of a crash)
        if ((unsigned)s >= (unsigned)N || (unsigned)d >= (unsigned)N) continue;
        const float* gp = &g_xw[(size_t)s * 128];
        float4 g0 = *(const float4*)&gp[tx * 4];
        float4 g1 = *(const float4*)&gp[64 + tx * 4];
        float v0 = fmaxf(acc[i][0] + g0.x, 0.f);
        float v1 = fmaxf(acc[i][1] + g0.y, 0.f);
        float v2 = fmaxf(acc[i][2] + g0.z, 0.f);
        float v3 = fmaxf(acc[i][3] + g0.w, 0.f);
        float v4 = fmaxf(acc[i][4] + g1.x, 0.f);
        float v5 = fmaxf(acc[i][5] + g1.y, 0.f);
        float v6 = fmaxf(acc[i][6] + g1.z, 0.f);
        float v7 = fmaxf(acc[i][7] + g1.w, 0.f);
        float* op = &out[(size_t)d * 128];
        red_add_v4(&op[tx * 4],      v0, v1, v2, v3);
        red_add_v4(&op[64 + tx * 4], v4, v5, v6, v7);
    }
}

extern "C" void kernel_launch(void* const* d_in, const int* in_sizes, int n_in,
                              void* d_out, int out_size) {
    const float* x    = (const float*)d_in[0];
    const int*   eidx = (const int*)d_in[1];   // int32 [2][E]
    const float* ea   = (const float*)d_in[2];
    const float* W    = (const float*)d_in[3];
    const float* b    = (const float*)d_in[4];
    float* out = (float*)d_out;

    const int N = in_sizes[0] / 128;   // 50000
    const int E = in_sizes[2] / 64;    // 800000

    const int node_smem = (128 * 64 + 64 * 128) * 4;            // 64 KB
    const int edge_smem = (64 * 128 + 128 * 64) * 4 + 256 * 4;  // 65 KB + idx

    cudaFuncSetAttribute(node_xw_kernel,
                         cudaFuncAttributeMaxDynamicSharedMemorySize, node_smem);
    cudaFuncSetAttribute(edge_kernel,
                         cudaFuncAttributeMaxDynamicSharedMemorySize, edge_smem);

    cudaMemsetAsync(d_out, 0, (size_t)out_size * sizeof(float), 0);

    node_xw_kernel<<<(N + 127) / 128, 256, node_smem>>>(x, W, b, N);
    edge_kernel<<<(E + 127) / 128, 256, edge_smem>>>(eidx, ea, W, out, E, N);
}